// round 1
// baseline (speedup 1.0000x reference)
#include <cuda_runtime.h>
#include <math.h>

#define NQ  4096
#define NKK 4096
#define DIM 1024

// Scratch (allocation-free rule: __device__ globals)
__device__ float g_kx[(size_t)NKK * DIM];
__device__ float g_qx[(size_t)NQ * DIM];
__device__ float g_sraw[(size_t)NQ * NKK];
__device__ float g_av[(size_t)NQ * DIM];

// ---------------------------------------------------------------------------
// Tiled fp32 GEMM: C[M,N] = A[M,K] @ op(B) (+ bias broadcast over rows)
//   BT=true : C[i,j] = sum_k A[i,k] * B[j,k]   (B is [N,K], "NT")
//   BT=false: C[i,j] = sum_k A[i,k] * B[k,j]   (B is [K,N], "NN")
// 128x128 block tile, K-tile 8, 256 threads, 8x8 per-thread microtile.
// M = gridDim.y*128, N/K passed. All dims multiples of 128/8 here.
// ---------------------------------------------------------------------------
template<bool BT>
__global__ __launch_bounds__(256)
void gemm128(const float* __restrict__ A, const float* __restrict__ B,
             const float* __restrict__ bias, float* __restrict__ C,
             int N, int K)
{
    __shared__ float As[8][128];
    __shared__ float Bs[8][128];
    const int tid  = threadIdx.x;
    const int row0 = blockIdx.y * 128;
    const int col0 = blockIdx.x * 128;
    const int tx = tid & 15, ty = tid >> 4;

    // A (and B in NT mode) load pattern: 128 rows x 8 k, float4 along k
    const int arow = tid >> 1;
    const int ak   = (tid & 1) << 2;
    // B in NN mode: 8 k-rows x 128 cols, float4 along cols
    const int bk2 = tid >> 5;
    const int bj  = (tid & 31) << 2;

    const float* Aldg = A + (size_t)(row0 + arow) * K + ak;
    const float* Bldg = BT ? (B + (size_t)(col0 + arow) * K + ak)
                           : (B + (size_t)bk2 * N + col0 + bj);

    float acc[8][8];
    #pragma unroll
    for (int i = 0; i < 8; i++)
        #pragma unroll
        for (int j = 0; j < 8; j++) acc[i][j] = 0.f;

    float4 aR = *(const float4*)(Aldg);
    float4 bR = BT ? *(const float4*)(Bldg) : *(const float4*)(Bldg);

    for (int k0 = 0; ; ) {
        As[ak + 0][arow] = aR.x; As[ak + 1][arow] = aR.y;
        As[ak + 2][arow] = aR.z; As[ak + 3][arow] = aR.w;
        if (BT) {
            Bs[ak + 0][arow] = bR.x; Bs[ak + 1][arow] = bR.y;
            Bs[ak + 2][arow] = bR.z; Bs[ak + 3][arow] = bR.w;
        } else {
            *(float4*)&Bs[bk2][bj] = bR;
        }
        __syncthreads();

        k0 += 8;
        const bool more = (k0 < K);
        if (more) {
            aR = *(const float4*)(Aldg + k0);
            bR = BT ? *(const float4*)(Bldg + k0)
                    : *(const float4*)(Bldg + (size_t)k0 * N);
        }

        #pragma unroll
        for (int kk = 0; kk < 8; kk++) {
            float a[8], b[8];
            *(float4*)&a[0] = *(const float4*)&As[kk][ty * 8];
            *(float4*)&a[4] = *(const float4*)&As[kk][ty * 8 + 4];
            *(float4*)&b[0] = *(const float4*)&Bs[kk][tx * 8];
            *(float4*)&b[4] = *(const float4*)&Bs[kk][tx * 8 + 4];
            #pragma unroll
            for (int i = 0; i < 8; i++)
                #pragma unroll
                for (int j = 0; j < 8; j++)
                    acc[i][j] = fmaf(a[i], b[j], acc[i][j]);
        }
        if (!more) break;
        __syncthreads();
    }

    // Epilogue (+ optional bias along columns)
    #pragma unroll
    for (int i = 0; i < 8; i++) {
        const int row = row0 + ty * 8 + i;
        float* Cr = C + (size_t)row * N + col0 + tx * 8;
        #pragma unroll
        for (int j = 0; j < 8; j += 4) {
            float b0 = 0.f, b1 = 0.f, b2 = 0.f, b3 = 0.f;
            if (bias) {
                const float* bpp = bias + col0 + tx * 8 + j;
                b0 = bpp[0]; b1 = bpp[1]; b2 = bpp[2]; b3 = bpp[3];
            }
            float4 v;
            v.x = acc[i][j + 0] + b0; v.y = acc[i][j + 1] + b1;
            v.z = acc[i][j + 2] + b2; v.w = acc[i][j + 3] + b3;
            *(float4*)(Cr + j) = v;
        }
    }
}

// ---------------------------------------------------------------------------
// Fused double masked softmax over one row of 4096:
//   s1 = softmax(sraw + bias),  s2 = softmax(s1*wei + bias),  bias=-inf @ mask==0
// One CTA (256 threads) per row; 16 elements per thread in registers.
// Mask kept as a register bitmask: an unmasked element whose s1 underflows to
// 0 must still contribute exp(0 - max2) in pass 2 (NOT be treated as masked).
// ---------------------------------------------------------------------------
__global__ __launch_bounds__(256)
void softmax2_kernel(const float* __restrict__ sraw, const int* __restrict__ mask,
                     const float* __restrict__ wei, float* __restrict__ sout)
{
    __shared__ float red[8];
    const int tid  = threadIdx.x;
    const int lane = tid & 31, wid = tid >> 5;
    const size_t base = (size_t)blockIdx.x * NKK;

    float sv[16], wv[16];
    unsigned mbits = 0u;
    float mx = -INFINITY;
    #pragma unroll
    for (int i = 0; i < 16; i++) {
        const int idx = tid + i * 256;
        float v = sraw[base + idx];
        const int mm = mask[base + idx];
        wv[i] = wei[base + idx];
        if (mm) mbits |= (1u << i); else v = -INFINITY;
        sv[i] = v;
        mx = fmaxf(mx, v);
    }
    #pragma unroll
    for (int o = 16; o; o >>= 1) mx = fmaxf(mx, __shfl_xor_sync(0xffffffffu, mx, o));
    if (lane == 0) red[wid] = mx;
    __syncthreads();
    mx = red[0];
    #pragma unroll
    for (int w = 1; w < 8; w++) mx = fmaxf(mx, red[w]);

    float sum = 0.f;
    #pragma unroll
    for (int i = 0; i < 16; i++) { float p = expf(sv[i] - mx); sv[i] = p; sum += p; }
    #pragma unroll
    for (int o = 16; o; o >>= 1) sum += __shfl_xor_sync(0xffffffffu, sum, o);
    __syncthreads();
    if (lane == 0) red[wid] = sum;
    __syncthreads();
    sum = 0.f;
    #pragma unroll
    for (int w = 0; w < 8; w++) sum += red[w];
    const float inv = 1.0f / sum;

    float mx2 = -INFINITY;
    #pragma unroll
    for (int i = 0; i < 16; i++) {
        const float t = ((mbits >> i) & 1u) ? sv[i] * inv * wv[i] : -INFINITY;
        sv[i] = t;
        mx2 = fmaxf(mx2, t);
    }
    #pragma unroll
    for (int o = 16; o; o >>= 1) mx2 = fmaxf(mx2, __shfl_xor_sync(0xffffffffu, mx2, o));
    __syncthreads();
    if (lane == 0) red[wid] = mx2;
    __syncthreads();
    mx2 = red[0];
    #pragma unroll
    for (int w = 1; w < 8; w++) mx2 = fmaxf(mx2, red[w]);

    float sum2 = 0.f;
    #pragma unroll
    for (int i = 0; i < 16; i++) { float p = expf(sv[i] - mx2); sv[i] = p; sum2 += p; }
    #pragma unroll
    for (int o = 16; o; o >>= 1) sum2 += __shfl_xor_sync(0xffffffffu, sum2, o);
    __syncthreads();
    if (lane == 0) red[wid] = sum2;
    __syncthreads();
    sum2 = 0.f;
    #pragma unroll
    for (int w = 0; w < 8; w++) sum2 += red[w];
    const float inv2 = 1.0f / sum2;

    #pragma unroll
    for (int i = 0; i < 16; i++)
        sout[base + tid + i * 256] = sv[i] * inv2;
}

// ---------------------------------------------------------------------------
extern "C" void kernel_launch(void* const* d_in, const int* in_sizes, int n_in,
                              void* d_out, int out_size)
{
    const float* q    = (const float*)d_in[0];
    const float* k    = (const float*)d_in[1];
    const int*   mask = (const int*)  d_in[2];
    const float* wei  = (const float*)d_in[3];
    const float* Wq   = (const float*)d_in[4];
    const float* bq   = (const float*)d_in[5];
    const float* Wk   = (const float*)d_in[6];
    const float* bk   = (const float*)d_in[7];
    const float* Wp   = (const float*)d_in[8];
    const float* bp   = (const float*)d_in[9];

    float* out_ptr   = (float*)d_out;                 // [NQ, DIM]
    float* score_out = out_ptr + (size_t)NQ * DIM;    // [NQ, NKK]

    float *kx, *qx, *sraw, *av;
    cudaGetSymbolAddress((void**)&kx,   g_kx);
    cudaGetSymbolAddress((void**)&qx,   g_qx);
    cudaGetSymbolAddress((void**)&sraw, g_sraw);
    cudaGetSymbolAddress((void**)&av,   g_av);

    const dim3 blk(256);
    // kx = k @ Wk^T + bk ; qx = q @ Wq^T + bq
    gemm128<true ><<<dim3(DIM / 128, NKK / 128), blk>>>(k,  Wk, bk, kx, DIM, DIM);
    gemm128<true ><<<dim3(DIM / 128, NQ  / 128), blk>>>(q,  Wq, bq, qx, DIM, DIM);
    // sraw = qx @ kx^T
    gemm128<true ><<<dim3(NKK / 128, NQ / 128), blk>>>(qx, kx, nullptr, sraw, NKK, DIM);
    // score (double masked softmax) -> directly into d_out score region
    softmax2_kernel<<<NQ, 256>>>(sraw, mask, wei, score_out);
    // av = score @ kx   (NN)
    gemm128<false><<<dim3(DIM / 128, NQ / 128), blk>>>(score_out, kx, nullptr, av, DIM, NKK);
    // out = av @ Wp^T + bp
    gemm128<true ><<<dim3(DIM / 128, NQ / 128), blk>>>(av, Wp, bp, out_ptr, DIM, DIM);
}

// round 3
// speedup vs baseline: 2.5996x; 2.5996x over previous
#include <cuda_runtime.h>
#include <cuda_bf16.h>
#include <math.h>
#include <stdint.h>

#define NQ  4096
#define NKK 4096
#define DIM 1024

typedef __nv_bfloat16 bf16;

// ---------------------------------------------------------------------------
// Scratch (__device__ globals; allocation-free rule)
// ---------------------------------------------------------------------------
__device__ __align__(16) bf16 g_qh [(size_t)NQ  * DIM];
__device__ __align__(16) bf16 g_ql [(size_t)NQ  * DIM];
__device__ __align__(16) bf16 g_kh [(size_t)NKK * DIM];
__device__ __align__(16) bf16 g_kl [(size_t)NKK * DIM];
__device__ __align__(16) bf16 g_Wqh[(size_t)DIM * DIM];
__device__ __align__(16) bf16 g_Wql[(size_t)DIM * DIM];
__device__ __align__(16) bf16 g_Wkh[(size_t)DIM * DIM];
__device__ __align__(16) bf16 g_Wkl[(size_t)DIM * DIM];
__device__ __align__(16) bf16 g_Wph[(size_t)DIM * DIM];
__device__ __align__(16) bf16 g_Wpl[(size_t)DIM * DIM];
__device__ __align__(16) bf16 g_qxh[(size_t)NQ  * DIM];
__device__ __align__(16) bf16 g_qxl[(size_t)NQ  * DIM];
__device__ __align__(16) bf16 g_kxh[(size_t)NKK * DIM];
__device__ __align__(16) bf16 g_kxl[(size_t)NKK * DIM];
__device__ __align__(16) bf16 g_kxTh[(size_t)DIM * NKK];
__device__ __align__(16) bf16 g_kxTl[(size_t)DIM * NKK];
__device__ __align__(16) bf16 g_sh [(size_t)NQ * NKK];
__device__ __align__(16) bf16 g_sl [(size_t)NQ * NKK];
__device__ __align__(16) bf16 g_avh[(size_t)NQ * DIM];
__device__ __align__(16) bf16 g_avl[(size_t)NQ * DIM];
__device__ float g_sraw[(size_t)NQ * NKK];

// ---------------------------------------------------------------------------
// Asm helpers (portable PTX only: sm_80-class — compiles under compute_103)
// ---------------------------------------------------------------------------
__device__ __forceinline__ uint32_t smem_u32(const void* p) {
    uint32_t a;
    asm("{ .reg .u64 t; cvta.to.shared.u64 t, %1; cvt.u32.u64 %0, t; }" : "=r"(a) : "l"(p));
    return a;
}
__device__ __forceinline__ void cpasync16(uint32_t dst, const void* src) {
    asm volatile("cp.async.cg.shared.global [%0], [%1], 16;" :: "r"(dst), "l"(src));
}
__device__ __forceinline__ void ldm4(uint32_t* r, uint32_t a) {
    asm volatile("ldmatrix.sync.aligned.m8n8.x4.shared.b16 {%0,%1,%2,%3}, [%4];"
                 : "=r"(r[0]), "=r"(r[1]), "=r"(r[2]), "=r"(r[3]) : "r"(a));
}
__device__ __forceinline__ void mma16816(float* c, const uint32_t* a,
                                         uint32_t b0, uint32_t b1) {
    asm volatile(
        "mma.sync.aligned.m16n8k16.row.col.f32.bf16.bf16.f32 "
        "{%0,%1,%2,%3}, {%4,%5,%6,%7}, {%8,%9}, {%0,%1,%2,%3};"
        : "+f"(c[0]), "+f"(c[1]), "+f"(c[2]), "+f"(c[3])
        : "r"(a[0]), "r"(a[1]), "r"(a[2]), "r"(a[3]), "r"(b0), "r"(b1));
}
__device__ __forceinline__ void split_bf16(float x, bf16& h, bf16& l) {
    h = __float2bfloat16_rn(x);
    l = __float2bfloat16_rn(x - __bfloat162float(h));
}

// ---------------------------------------------------------------------------
// GEMM: C[M,N] = (Ah+Al)[M,K] @ (Bh+Bl)[N,K]^T  (3-term split, fp32 acc)
// Outputs: optional fp32 Cf, optional bf16 pair (Ch, Cl). Optional bias (cols).
// 128x128x32 tiles, 256 threads, cp.async 3-stage, swizzled smem, ldmatrix.
// Smem tile layout: row r (0..127) has 8 16B units; logical unit j (0-3 = hi
// k-halves, 4-7 = lo k-halves) stored at slot j^(r&7).
// ---------------------------------------------------------------------------
#define BM 128
#define BN 128
#define BK 32
#define STAGES 3
#define ATILEB 16384
#define STAGEB 32768
#define SMEM_DYN (STAGES * STAGEB + 1024)

struct GemmTiles { const bf16 *Ah, *Al, *Bh, *Bl; };

__device__ __forceinline__ void issue_stage(
    uint32_t smem0, int stage, int kc, int tid, int row0, int col0, int K,
    const bf16* Ah, const bf16* Al, const bf16* Bh, const bf16* Bl)
{
    const uint32_t sb = smem0 + stage * STAGEB;
    #pragma unroll
    for (int t = 0; t < 4; t++) {
        const int u = tid + t * 256;
        const int r = u >> 3, j = u & 7;
        const bf16* src = ((j & 4) ? Al : Ah) + (size_t)(row0 + r) * K + kc * BK + (j & 3) * 8;
        cpasync16(sb + r * 128 + ((j ^ (r & 7)) * 16), src);
    }
    #pragma unroll
    for (int t = 0; t < 4; t++) {
        const int u = tid + t * 256;
        const int r = u >> 3, j = u & 7;
        const bf16* src = ((j & 4) ? Bl : Bh) + (size_t)(col0 + r) * K + kc * BK + (j & 3) * 8;
        cpasync16(sb + ATILEB + r * 128 + ((j ^ (r & 7)) * 16), src);
    }
    asm volatile("cp.async.commit_group;" ::: "memory");
}

__global__ __launch_bounds__(256, 1)
void gemm_mma(const bf16* __restrict__ Ah, const bf16* __restrict__ Al,
              const bf16* __restrict__ Bh, const bf16* __restrict__ Bl,
              const float* __restrict__ bias,
              float* __restrict__ Cf,
              bf16* __restrict__ Ch, bf16* __restrict__ Cl,
              int N, int K)
{
    extern __shared__ char dynsmem[];
    const uint32_t dynb = smem_u32(dynsmem);
    const uint32_t smem0 = (dynb + 1023u) & ~1023u;

    const int tid  = threadIdx.x;
    const int lane = tid & 31;
    const int w    = tid >> 5;
    const int wm   = w >> 2;      // 0..1
    const int wn   = w & 3;       // 0..3
    const int row0 = blockIdx.y * BM;
    const int col0 = blockIdx.x * BN;
    const int KT   = K / BK;

    float acc[4][4][4];
    #pragma unroll
    for (int i = 0; i < 4; i++)
        #pragma unroll
        for (int j = 0; j < 4; j++)
            #pragma unroll
            for (int r = 0; r < 4; r++) acc[i][j][r] = 0.f;

    issue_stage(smem0, 0, 0, tid, row0, col0, K, Ah, Al, Bh, Bl);
    issue_stage(smem0, 1, 1, tid, row0, col0, K, Ah, Al, Bh, Bl);

    for (int kc = 0; kc < KT; kc++) {
        asm volatile("cp.async.wait_group %0;" :: "n"(STAGES - 2) : "memory");
        __syncthreads();
        const uint32_t sa  = smem0 + (kc % STAGES) * STAGEB;
        const uint32_t sbt = sa + ATILEB;

        #pragma unroll
        for (int ks = 0; ks < 2; ks++) {
            uint32_t ahf[4][4], alf[4][4], bhf[2][4], blf[2][4];
            #pragma unroll
            for (int mf = 0; mf < 4; mf++) {
                const int r  = wm * 64 + mf * 16 + (lane & 15);
                const int jh = ks * 2 + (lane >> 4);
                ldm4(ahf[mf], sa + r * 128 + ((jh ^ (r & 7)) * 16));
                ldm4(alf[mf], sa + r * 128 + (((jh + 4) ^ (r & 7)) * 16));
            }
            #pragma unroll
            for (int nb = 0; nb < 2; nb++) {
                const int r  = wn * 32 + nb * 16 + (lane & 7) + ((lane & 16) >> 1);
                const int jh = ks * 2 + ((lane >> 3) & 1);
                ldm4(bhf[nb], sbt + r * 128 + ((jh ^ (r & 7)) * 16));
                ldm4(blf[nb], sbt + r * 128 + (((jh + 4) ^ (r & 7)) * 16));
            }
            #pragma unroll
            for (int mf = 0; mf < 4; mf++)
                #pragma unroll
                for (int nf = 0; nf < 4; nf++) {
                    const uint32_t b0 = bhf[nf >> 1][(nf & 1) * 2];
                    const uint32_t b1 = bhf[nf >> 1][(nf & 1) * 2 + 1];
                    const uint32_t l0 = blf[nf >> 1][(nf & 1) * 2];
                    const uint32_t l1 = blf[nf >> 1][(nf & 1) * 2 + 1];
                    mma16816(acc[mf][nf], ahf[mf], b0, b1);
                    mma16816(acc[mf][nf], ahf[mf], l0, l1);
                    mma16816(acc[mf][nf], alf[mf], b0, b1);
                }
        }
        __syncthreads();
        if (kc + STAGES - 1 < KT)
            issue_stage(smem0, (kc + STAGES - 1) % STAGES, kc + STAGES - 1,
                        tid, row0, col0, K, Ah, Al, Bh, Bl);
    }
    asm volatile("cp.async.wait_group 0;" ::: "memory");

    // Epilogue
    #pragma unroll
    for (int mf = 0; mf < 4; mf++) {
        #pragma unroll
        for (int nf = 0; nf < 4; nf++) {
            const int rg = row0 + wm * 64 + mf * 16 + (lane >> 2);
            const int cg = col0 + wn * 32 + nf * 8 + (lane & 3) * 2;
            float v0 = acc[mf][nf][0], v1 = acc[mf][nf][1];
            float v2 = acc[mf][nf][2], v3 = acc[mf][nf][3];
            if (bias) {
                const float b0 = bias[cg], b1 = bias[cg + 1];
                v0 += b0; v1 += b1; v2 += b0; v3 += b1;
            }
            if (Cf) {
                float2 p0 = make_float2(v0, v1), p1 = make_float2(v2, v3);
                *(float2*)&Cf[(size_t)rg * N + cg]       = p0;
                *(float2*)&Cf[(size_t)(rg + 8) * N + cg] = p1;
            }
            if (Ch) {
                bf16 h0, l0, h1, l1, h2, l2, h3, l3;
                split_bf16(v0, h0, l0); split_bf16(v1, h1, l1);
                split_bf16(v2, h2, l2); split_bf16(v3, h3, l3);
                __nv_bfloat162 hh0; hh0.x = h0; hh0.y = h1;
                __nv_bfloat162 hh1; hh1.x = h2; hh1.y = h3;
                __nv_bfloat162 ll0; ll0.x = l0; ll0.y = l1;
                __nv_bfloat162 ll1; ll1.x = l2; ll1.y = l3;
                *(__nv_bfloat162*)&Ch[(size_t)rg * N + cg]       = hh0;
                *(__nv_bfloat162*)&Ch[(size_t)(rg + 8) * N + cg] = hh1;
                *(__nv_bfloat162*)&Cl[(size_t)rg * N + cg]       = ll0;
                *(__nv_bfloat162*)&Cl[(size_t)(rg + 8) * N + cg] = ll1;
            }
        }
    }
}

// ---------------------------------------------------------------------------
// fp32 -> bf16 hi/lo pair conversion (elementwise, float4-vectorized)
// ---------------------------------------------------------------------------
__global__ __launch_bounds__(256)
void conv_pair(const float* __restrict__ x, bf16* __restrict__ h,
               bf16* __restrict__ l, int n4)
{
    const int i = blockIdx.x * 256 + threadIdx.x;
    if (i >= n4) return;
    const float4 v = ((const float4*)x)[i];
    bf16 h0, l0, h1, l1, h2, l2, h3, l3;
    split_bf16(v.x, h0, l0); split_bf16(v.y, h1, l1);
    split_bf16(v.z, h2, l2); split_bf16(v.w, h3, l3);
    __nv_bfloat162 a; a.x = h0; a.y = h1;
    __nv_bfloat162 b; b.x = h2; b.y = h3;
    __nv_bfloat162 c; c.x = l0; c.y = l1;
    __nv_bfloat162 d; d.x = l2; d.y = l3;
    ((__nv_bfloat162*)h)[i * 2]     = a;
    ((__nv_bfloat162*)h)[i * 2 + 1] = b;
    ((__nv_bfloat162*)l)[i * 2]     = c;
    ((__nv_bfloat162*)l)[i * 2 + 1] = d;
}

// ---------------------------------------------------------------------------
// bf16 transpose: out[c][r] = in[r][c]; in [R][C]
// ---------------------------------------------------------------------------
__global__ __launch_bounds__(256)
void transpose_bf16(const bf16* __restrict__ in, bf16* __restrict__ out,
                    int R, int C)
{
    __shared__ bf16 t[32][33];
    const int bx = blockIdx.x * 32, by = blockIdx.y * 32;
    int x = bx + threadIdx.x;
    #pragma unroll
    for (int i = 0; i < 32; i += 8)
        t[threadIdx.y + i][threadIdx.x] = in[(size_t)(by + threadIdx.y + i) * C + x];
    __syncthreads();
    x = by + threadIdx.x;
    #pragma unroll
    for (int i = 0; i < 32; i += 8)
        out[(size_t)(bx + threadIdx.y + i) * R + x] = t[threadIdx.x][threadIdx.y + i];
}

// ---------------------------------------------------------------------------
// Fused double masked softmax; writes fp32 score + bf16 hi/lo pair.
// ---------------------------------------------------------------------------
__global__ __launch_bounds__(256)
void softmax2_kernel(const float* __restrict__ sraw, const int* __restrict__ mask,
                     const float* __restrict__ wei, float* __restrict__ sout,
                     bf16* __restrict__ sh, bf16* __restrict__ sl)
{
    __shared__ float red[8];
    const int tid  = threadIdx.x;
    const int lane = tid & 31, wid = tid >> 5;
    const size_t base = (size_t)blockIdx.x * NKK;

    float sv[16], wv[16];
    unsigned mbits = 0u;
    float mx = -INFINITY;
    #pragma unroll
    for (int i = 0; i < 16; i++) {
        const int idx = tid + i * 256;
        float v = sraw[base + idx];
        const int mm = mask[base + idx];
        wv[i] = wei[base + idx];
        if (mm) mbits |= (1u << i); else v = -INFINITY;
        sv[i] = v;
        mx = fmaxf(mx, v);
    }
    #pragma unroll
    for (int o = 16; o; o >>= 1) mx = fmaxf(mx, __shfl_xor_sync(0xffffffffu, mx, o));
    if (lane == 0) red[wid] = mx;
    __syncthreads();
    mx = red[0];
    #pragma unroll
    for (int w = 1; w < 8; w++) mx = fmaxf(mx, red[w]);

    float sum = 0.f;
    #pragma unroll
    for (int i = 0; i < 16; i++) { float p = expf(sv[i] - mx); sv[i] = p; sum += p; }
    #pragma unroll
    for (int o = 16; o; o >>= 1) sum += __shfl_xor_sync(0xffffffffu, sum, o);
    __syncthreads();
    if (lane == 0) red[wid] = sum;
    __syncthreads();
    sum = 0.f;
    #pragma unroll
    for (int w = 0; w < 8; w++) sum += red[w];
    const float inv = 1.0f / sum;

    float mx2 = -INFINITY;
    #pragma unroll
    for (int i = 0; i < 16; i++) {
        const float t = ((mbits >> i) & 1u) ? sv[i] * inv * wv[i] : -INFINITY;
        sv[i] = t;
        mx2 = fmaxf(mx2, t);
    }
    #pragma unroll
    for (int o = 16; o; o >>= 1) mx2 = fmaxf(mx2, __shfl_xor_sync(0xffffffffu, mx2, o));
    __syncthreads();
    if (lane == 0) red[wid] = mx2;
    __syncthreads();
    mx2 = red[0];
    #pragma unroll
    for (int w = 1; w < 8; w++) mx2 = fmaxf(mx2, red[w]);

    float sum2 = 0.f;
    #pragma unroll
    for (int i = 0; i < 16; i++) { float p = expf(sv[i] - mx2); sv[i] = p; sum2 += p; }
    #pragma unroll
    for (int o = 16; o; o >>= 1) sum2 += __shfl_xor_sync(0xffffffffu, sum2, o);
    __syncthreads();
    if (lane == 0) red[wid] = sum2;
    __syncthreads();
    sum2 = 0.f;
    #pragma unroll
    for (int w = 0; w < 8; w++) sum2 += red[w];
    const float inv2 = 1.0f / sum2;

    #pragma unroll
    for (int i = 0; i < 16; i++) {
        const float p = sv[i] * inv2;
        const int idx = tid + i * 256;
        sout[base + idx] = p;
        bf16 h, l;
        split_bf16(p, h, l);
        sh[base + idx] = h;
        sl[base + idx] = l;
    }
}

// ---------------------------------------------------------------------------
extern "C" void kernel_launch(void* const* d_in, const int* in_sizes, int n_in,
                              void* d_out, int out_size)
{
    const float* q    = (const float*)d_in[0];
    const float* k    = (const float*)d_in[1];
    const int*   mask = (const int*)  d_in[2];
    const float* wei  = (const float*)d_in[3];
    const float* Wq   = (const float*)d_in[4];
    const float* bq   = (const float*)d_in[5];
    const float* Wk   = (const float*)d_in[6];
    const float* bk   = (const float*)d_in[7];
    const float* Wp   = (const float*)d_in[8];
    const float* bp   = (const float*)d_in[9];

    float* out_ptr   = (float*)d_out;                 // [NQ, DIM]
    float* score_out = out_ptr + (size_t)NQ * DIM;    // [NQ, NKK]

    bf16 *qh, *ql, *kh, *kl, *Wqh, *Wql, *Wkh, *Wkl, *Wph, *Wpl;
    bf16 *qxh, *qxl, *kxh, *kxl, *kxTh, *kxTl, *sh, *sl, *avh, *avl;
    float* sraw;
    cudaGetSymbolAddress((void**)&qh, g_qh);   cudaGetSymbolAddress((void**)&ql, g_ql);
    cudaGetSymbolAddress((void**)&kh, g_kh);   cudaGetSymbolAddress((void**)&kl, g_kl);
    cudaGetSymbolAddress((void**)&Wqh, g_Wqh); cudaGetSymbolAddress((void**)&Wql, g_Wql);
    cudaGetSymbolAddress((void**)&Wkh, g_Wkh); cudaGetSymbolAddress((void**)&Wkl, g_Wkl);
    cudaGetSymbolAddress((void**)&Wph, g_Wph); cudaGetSymbolAddress((void**)&Wpl, g_Wpl);
    cudaGetSymbolAddress((void**)&qxh, g_qxh); cudaGetSymbolAddress((void**)&qxl, g_qxl);
    cudaGetSymbolAddress((void**)&kxh, g_kxh); cudaGetSymbolAddress((void**)&kxl, g_kxl);
    cudaGetSymbolAddress((void**)&kxTh, g_kxTh); cudaGetSymbolAddress((void**)&kxTl, g_kxTl);
    cudaGetSymbolAddress((void**)&sh, g_sh);   cudaGetSymbolAddress((void**)&sl, g_sl);
    cudaGetSymbolAddress((void**)&avh, g_avh); cudaGetSymbolAddress((void**)&avl, g_avl);
    cudaGetSymbolAddress((void**)&sraw, g_sraw);

    static bool attr_done = false;
    if (!attr_done) {
        cudaFuncSetAttribute(gemm_mma, cudaFuncAttributeMaxDynamicSharedMemorySize, SMEM_DYN);
        attr_done = true;
    }

    // Convert external fp32 operands to bf16 hi/lo pairs
    conv_pair<<<(NQ * DIM / 4 + 255) / 256, 256>>>(q, qh, ql, NQ * DIM / 4);
    conv_pair<<<(NKK * DIM / 4 + 255) / 256, 256>>>(k, kh, kl, NKK * DIM / 4);
    conv_pair<<<(DIM * DIM / 4 + 255) / 256, 256>>>(Wq, Wqh, Wql, DIM * DIM / 4);
    conv_pair<<<(DIM * DIM / 4 + 255) / 256, 256>>>(Wk, Wkh, Wkl, DIM * DIM / 4);
    conv_pair<<<(DIM * DIM / 4 + 255) / 256, 256>>>(Wp, Wph, Wpl, DIM * DIM / 4);

    const dim3 blk(256);
    // kx = k @ Wk^T + bk  -> bf16 pair
    gemm_mma<<<dim3(DIM / BN, NKK / BM), blk, SMEM_DYN>>>(
        kh, kl, Wkh, Wkl, bk, nullptr, kxh, kxl, DIM, DIM);
    // qx = q @ Wq^T + bq  -> bf16 pair
    gemm_mma<<<dim3(DIM / BN, NQ / BM), blk, SMEM_DYN>>>(
        qh, ql, Wqh, Wql, bq, nullptr, qxh, qxl, DIM, DIM);
    // kxT pair (for AV GEMM B-side, [DIM][NKK])
    transpose_bf16<<<dim3(DIM / 32, NKK / 32), dim3(32, 8)>>>(kxh, kxTh, NKK, DIM);
    transpose_bf16<<<dim3(DIM / 32, NKK / 32), dim3(32, 8)>>>(kxl, kxTl, NKK, DIM);
    // sraw = qx @ kx^T  -> fp32
    gemm_mma<<<dim3(NKK / BN, NQ / BM), blk, SMEM_DYN>>>(
        qxh, qxl, kxh, kxl, nullptr, sraw, nullptr, nullptr, NKK, DIM);
    // score = double masked softmax -> fp32 (d_out) + bf16 pair
    softmax2_kernel<<<NQ, 256>>>(sraw, mask, wei, score_out, sh, sl);
    // av = score @ kx  (= score @ kxT^T, NT)  -> bf16 pair
    gemm_mma<<<dim3(DIM / BN, NQ / BM), blk, SMEM_DYN>>>(
        sh, sl, kxTh, kxTl, nullptr, nullptr, avh, avl, DIM, NKK);
    // out = av @ Wp^T + bp -> fp32 (d_out)
    gemm_mma<<<dim3(DIM / BN, NQ / BM), blk, SMEM_DYN>>>(
        avh, avl, Wph, Wpl, bp, out_ptr, nullptr, nullptr, DIM, DIM);
}

// round 6
// speedup vs baseline: 3.0971x; 1.1914x over previous
#include <cuda_runtime.h>
#include <cuda_bf16.h>
#include <math.h>
#include <stdint.h>

#define NQ  4096
#define NKK 4096
#define DIM 1024

typedef __nv_bfloat16 bf16;

// ---------------------------------------------------------------------------
// Scratch (__device__ globals; allocation-free rule)
// ---------------------------------------------------------------------------
__device__ __align__(16) bf16 g_qh [(size_t)NQ  * DIM];
__device__ __align__(16) bf16 g_ql [(size_t)NQ  * DIM];
__device__ __align__(16) bf16 g_kh [(size_t)NKK * DIM];
__device__ __align__(16) bf16 g_kl [(size_t)NKK * DIM];
__device__ __align__(16) bf16 g_Wqh[(size_t)DIM * DIM];
__device__ __align__(16) bf16 g_Wql[(size_t)DIM * DIM];
__device__ __align__(16) bf16 g_Wkh[(size_t)DIM * DIM];
__device__ __align__(16) bf16 g_Wkl[(size_t)DIM * DIM];
__device__ __align__(16) bf16 g_Wph[(size_t)DIM * DIM];
__device__ __align__(16) bf16 g_Wpl[(size_t)DIM * DIM];
__device__ __align__(16) bf16 g_qxh[(size_t)NQ  * DIM];
__device__ __align__(16) bf16 g_qxl[(size_t)NQ  * DIM];
__device__ __align__(16) bf16 g_kxh[(size_t)NKK * DIM];
__device__ __align__(16) bf16 g_kxl[(size_t)NKK * DIM];
__device__ __align__(16) bf16 g_kxTh[(size_t)DIM * NKK];
__device__ __align__(16) bf16 g_kxTl[(size_t)DIM * NKK];
__device__ __align__(16) bf16 g_sh [(size_t)NQ * NKK];
__device__ __align__(16) bf16 g_sl [(size_t)NQ * NKK];
__device__ __align__(16) bf16 g_avh[(size_t)NQ * DIM];
__device__ __align__(16) bf16 g_avl[(size_t)NQ * DIM];
__device__ float g_sraw[(size_t)NQ * NKK];

// ---------------------------------------------------------------------------
// Asm helpers (portable sm_80-class PTX; compiles under compute_103)
// ---------------------------------------------------------------------------
__device__ __forceinline__ uint32_t smem_u32(const void* p) {
    uint32_t a;
    asm("{ .reg .u64 t; cvta.to.shared.u64 t, %1; cvt.u32.u64 %0, t; }" : "=r"(a) : "l"(p));
    return a;
}
__device__ __forceinline__ void cpasync16(uint32_t dst, const void* src) {
    asm volatile("cp.async.cg.shared.global [%0], [%1], 16;" :: "r"(dst), "l"(src));
}
__device__ __forceinline__ void ldm4(uint32_t* r, uint32_t a) {
    asm volatile("ldmatrix.sync.aligned.m8n8.x4.shared.b16 {%0,%1,%2,%3}, [%4];"
                 : "=r"(r[0]), "=r"(r[1]), "=r"(r[2]), "=r"(r[3]) : "r"(a));
}
__device__ __forceinline__ void mma16816(float* c, const uint32_t* a,
                                         uint32_t b0, uint32_t b1) {
    asm volatile(
        "mma.sync.aligned.m16n8k16.row.col.f32.bf16.bf16.f32 "
        "{%0,%1,%2,%3}, {%4,%5,%6,%7}, {%8,%9}, {%0,%1,%2,%3};"
        : "+f"(c[0]), "+f"(c[1]), "+f"(c[2]), "+f"(c[3])
        : "r"(a[0]), "r"(a[1]), "r"(a[2]), "r"(a[3]), "r"(b0), "r"(b1));
}
__device__ __forceinline__ void split_bf16(float x, bf16& h, bf16& l) {
    h = __float2bfloat16_rn(x);
    l = __float2bfloat16_rn(x - __bfloat162float(h));
}

// ---------------------------------------------------------------------------
// GEMM: C[M,N] = (Ah+Al)[M,K] @ (Bh+Bl)[N,K]^T  (3-term split, fp32 acc)
// 128x128x64 tiles, 256 threads, cp.async 3-stage, swizzled smem, ldmatrix.
// Smem row (per tile): 256B = 16x16B units; hi half units 0-7, lo 8-15.
// Unit j stored at slot (j&8) | ((j&7) ^ (r&7)).
// One __syncthreads per chunk; next stage issued right after it.
// ---------------------------------------------------------------------------
#define BM 128
#define BN 128
#define BK 64
#define STAGES 3
#define ROWB 256
#define ATILEB (BM * ROWB)            // 32 KB
#define STAGEB (2 * ATILEB)           // 64 KB
#define SMEM_DYN (STAGES * STAGEB + 1024)

__device__ __forceinline__ void issue_stage64(
    uint32_t smem0, int stage, int kc, int tid, int row0, int col0, int K,
    const bf16* Ah, const bf16* Al, const bf16* Bh, const bf16* Bl)
{
    const uint32_t sb = smem0 + stage * STAGEB;
    #pragma unroll
    for (int t = 0; t < 8; t++) {
        const int u = tid + t * 256;
        const int r = u >> 4, j = u & 15;
        const bf16* src = ((j & 8) ? Al : Ah) + (size_t)(row0 + r) * K + kc * BK + (j & 7) * 8;
        cpasync16(sb + r * ROWB + (((j & 8) | ((j & 7) ^ (r & 7))) * 16), src);
    }
    #pragma unroll
    for (int t = 0; t < 8; t++) {
        const int u = tid + t * 256;
        const int r = u >> 4, j = u & 15;
        const bf16* src = ((j & 8) ? Bl : Bh) + (size_t)(col0 + r) * K + kc * BK + (j & 7) * 8;
        cpasync16(sb + ATILEB + r * ROWB + (((j & 8) | ((j & 7) ^ (r & 7))) * 16), src);
    }
    asm volatile("cp.async.commit_group;" ::: "memory");
}

__device__ __forceinline__ void gemm_body(
    const bf16* __restrict__ Ah, const bf16* __restrict__ Al,
    const bf16* __restrict__ Bh, const bf16* __restrict__ Bl,
    const float* __restrict__ bias,
    float* __restrict__ Cf, bf16* __restrict__ Ch, bf16* __restrict__ Cl,
    int N, int K, int row0, int col0)
{
    extern __shared__ char dynsmem[];
    const uint32_t dynb = smem_u32(dynsmem);
    const uint32_t smem0 = (dynb + 1023u) & ~1023u;

    const int tid  = threadIdx.x;
    const int lane = tid & 31;
    const int w    = tid >> 5;
    const int wm   = w >> 2;      // 0..1
    const int wn   = w & 3;       // 0..3
    const int KT   = K / BK;

    float acc[4][4][4];
    #pragma unroll
    for (int i = 0; i < 4; i++)
        #pragma unroll
        for (int j = 0; j < 4; j++)
            #pragma unroll
            for (int r = 0; r < 4; r++) acc[i][j][r] = 0.f;

    issue_stage64(smem0, 0, 0, tid, row0, col0, K, Ah, Al, Bh, Bl);
    issue_stage64(smem0, 1, 1, tid, row0, col0, K, Ah, Al, Bh, Bl);

    for (int kc = 0; kc < KT; kc++) {
        asm volatile("cp.async.wait_group %0;" :: "n"(STAGES - 2) : "memory");
        __syncthreads();
        // Safe: all warps finished chunk kc-1 compute; stage (kc+2)%3==(kc-1)%3.
        if (kc + 2 < KT)
            issue_stage64(smem0, (kc + 2) % STAGES, kc + 2, tid, row0, col0, K,
                          Ah, Al, Bh, Bl);
        const uint32_t sa  = smem0 + (kc % STAGES) * STAGEB;
        const uint32_t sbt = sa + ATILEB;

        #pragma unroll
        for (int ks = 0; ks < 4; ks++) {
            uint32_t ahf[4][4], alf[4][4], bhf[2][4], blf[2][4];
            #pragma unroll
            for (int mf = 0; mf < 4; mf++) {
                const int r  = wm * 64 + mf * 16 + (lane & 15);
                const int jh = ks * 2 + (lane >> 4);
                ldm4(ahf[mf], sa + r * ROWB + ((jh ^ (r & 7)) * 16));
                ldm4(alf[mf], sa + r * ROWB + ((8 | (jh ^ (r & 7))) * 16));
            }
            #pragma unroll
            for (int nb = 0; nb < 2; nb++) {
                const int r  = wn * 32 + nb * 16 + (lane & 7) + ((lane & 16) >> 1);
                const int jh = ks * 2 + ((lane >> 3) & 1);
                ldm4(bhf[nb], sbt + r * ROWB + ((jh ^ (r & 7)) * 16));
                ldm4(blf[nb], sbt + r * ROWB + ((8 | (jh ^ (r & 7))) * 16));
            }
            #pragma unroll
            for (int mf = 0; mf < 4; mf++)
                #pragma unroll
                for (int nf = 0; nf < 4; nf++) {
                    const uint32_t b0 = bhf[nf >> 1][(nf & 1) * 2];
                    const uint32_t b1 = bhf[nf >> 1][(nf & 1) * 2 + 1];
                    const uint32_t l0 = blf[nf >> 1][(nf & 1) * 2];
                    const uint32_t l1 = blf[nf >> 1][(nf & 1) * 2 + 1];
                    mma16816(acc[mf][nf], ahf[mf], b0, b1);
                    mma16816(acc[mf][nf], ahf[mf], l0, l1);
                    mma16816(acc[mf][nf], alf[mf], b0, b1);
                }
        }
    }
    asm volatile("cp.async.wait_group 0;" ::: "memory");

    // Epilogue
    #pragma unroll
    for (int mf = 0; mf < 4; mf++) {
        #pragma unroll
        for (int nf = 0; nf < 4; nf++) {
            const int rg = row0 + wm * 64 + mf * 16 + (lane >> 2);
            const int cg = col0 + wn * 32 + nf * 8 + (lane & 3) * 2;
            float v0 = acc[mf][nf][0], v1 = acc[mf][nf][1];
            float v2 = acc[mf][nf][2], v3 = acc[mf][nf][3];
            if (bias) {
                const float b0 = bias[cg], b1 = bias[cg + 1];
                v0 += b0; v1 += b1; v2 += b0; v3 += b1;
            }
            if (Cf) {
                *(float2*)&Cf[(size_t)rg * N + cg]       = make_float2(v0, v1);
                *(float2*)&Cf[(size_t)(rg + 8) * N + cg] = make_float2(v2, v3);
            }
            if (Ch) {
                bf16 h0, l0, h1, l1, h2, l2, h3, l3;
                split_bf16(v0, h0, l0); split_bf16(v1, h1, l1);
                split_bf16(v2, h2, l2); split_bf16(v3, h3, l3);
                __nv_bfloat162 hh0; hh0.x = h0; hh0.y = h1;
                __nv_bfloat162 hh1; hh1.x = h2; hh1.y = h3;
                __nv_bfloat162 ll0; ll0.x = l0; ll0.y = l1;
                __nv_bfloat162 ll1; ll1.x = l2; ll1.y = l3;
                *(__nv_bfloat162*)&Ch[(size_t)rg * N + cg]       = hh0;
                *(__nv_bfloat162*)&Ch[(size_t)(rg + 8) * N + cg] = hh1;
                *(__nv_bfloat162*)&Cl[(size_t)rg * N + cg]       = ll0;
                *(__nv_bfloat162*)&Cl[(size_t)(rg + 8) * N + cg] = ll1;
            }
        }
    }
}

__global__ __launch_bounds__(256, 1)
void gemm_mma(const bf16* __restrict__ Ah, const bf16* __restrict__ Al,
              const bf16* __restrict__ Bh, const bf16* __restrict__ Bl,
              const float* __restrict__ bias,
              float* __restrict__ Cf, bf16* __restrict__ Ch, bf16* __restrict__ Cl,
              int N, int K)
{
    gemm_body(Ah, Al, Bh, Bl, bias, Cf, Ch, Cl, N, K,
              blockIdx.y * BM, blockIdx.x * BN);
}

// Both projections (kx and qx) in one launch; z selects operand set.
__global__ __launch_bounds__(256, 1)
void gemm_proj(const bf16* __restrict__ kh, const bf16* __restrict__ kl,
               const bf16* __restrict__ Wkh, const bf16* __restrict__ Wkl,
               const float* __restrict__ bk, bf16* __restrict__ kxh, bf16* __restrict__ kxl,
               const bf16* __restrict__ qh, const bf16* __restrict__ ql,
               const bf16* __restrict__ Wqh, const bf16* __restrict__ Wql,
               const float* __restrict__ bq, bf16* __restrict__ qxh, bf16* __restrict__ qxl)
{
    if (blockIdx.z == 0)
        gemm_body(kh, kl, Wkh, Wkl, bk, nullptr, kxh, kxl, DIM, DIM,
                  blockIdx.y * BM, blockIdx.x * BN);
    else
        gemm_body(qh, ql, Wqh, Wql, bq, nullptr, qxh, qxl, DIM, DIM,
                  blockIdx.y * BM, blockIdx.x * BN);
}

// ---------------------------------------------------------------------------
// Fused fp32 -> bf16 hi/lo conversion for all 5 fp32 inputs (segmented grid).
// Blocks: [0,4096) q | [4096,8192) k | +1024 each for Wq, Wk, Wp.
// ---------------------------------------------------------------------------
__global__ __launch_bounds__(256)
void conv_all(const float* __restrict__ q, const float* __restrict__ k,
              const float* __restrict__ Wq, const float* __restrict__ Wk,
              const float* __restrict__ Wp,
              bf16* qh, bf16* ql, bf16* kh, bf16* kl,
              bf16* Wqh, bf16* Wql, bf16* Wkh, bf16* Wkl,
              bf16* Wph, bf16* Wpl)
{
    const int b = blockIdx.x;
    const float* src; bf16 *h, *l; int base;
    if      (b < 4096)  { src = q;  h = qh;  l = ql;  base = b; }
    else if (b < 8192)  { src = k;  h = kh;  l = kl;  base = b - 4096; }
    else if (b < 9216)  { src = Wq; h = Wqh; l = Wql; base = b - 8192; }
    else if (b < 10240) { src = Wk; h = Wkh; l = Wkl; base = b - 9216; }
    else                { src = Wp; h = Wph; l = Wpl; base = b - 10240; }
    const int i = base * 256 + threadIdx.x;
    const float4 v = ((const float4*)src)[i];
    bf16 h0, l0, h1, l1, h2, l2, h3, l3;
    split_bf16(v.x, h0, l0); split_bf16(v.y, h1, l1);
    split_bf16(v.z, h2, l2); split_bf16(v.w, h3, l3);
    __nv_bfloat162 a; a.x = h0; a.y = h1;
    __nv_bfloat162 bb; bb.x = h2; bb.y = h3;
    __nv_bfloat162 c; c.x = l0; c.y = l1;
    __nv_bfloat162 d; d.x = l2; d.y = l3;
    ((__nv_bfloat162*)h)[i * 2]     = a;
    ((__nv_bfloat162*)h)[i * 2 + 1] = bb;
    ((__nv_bfloat162*)l)[i * 2]     = c;
    ((__nv_bfloat162*)l)[i * 2 + 1] = d;
}

// ---------------------------------------------------------------------------
// bf16 transpose (h and l planes in one launch via z)
// ---------------------------------------------------------------------------
__global__ __launch_bounds__(256)
void transpose2_bf16(const bf16* __restrict__ inH, bf16* __restrict__ outH,
                     const bf16* __restrict__ inL, bf16* __restrict__ outL,
                     int R, int C)
{
    __shared__ bf16 t[32][33];
    const bf16* in  = blockIdx.z ? inL  : inH;
    bf16*       out = blockIdx.z ? outL : outH;
    const int bx = blockIdx.x * 32, by = blockIdx.y * 32;
    int x = bx + threadIdx.x;
    #pragma unroll
    for (int i = 0; i < 32; i += 8)
        t[threadIdx.y + i][threadIdx.x] = in[(size_t)(by + threadIdx.y + i) * C + x];
    __syncthreads();
    x = by + threadIdx.x;
    #pragma unroll
    for (int i = 0; i < 32; i += 8)
        out[(size_t)(bx + threadIdx.y + i) * R + x] = t[threadIdx.x][threadIdx.y + i];
}

// ---------------------------------------------------------------------------
// Fused double masked softmax; writes fp32 score + bf16 hi/lo pair.
// ---------------------------------------------------------------------------
__global__ __launch_bounds__(256)
void softmax2_kernel(const float* __restrict__ sraw, const int* __restrict__ mask,
                     const float* __restrict__ wei, float* __restrict__ sout,
                     bf16* __restrict__ sh, bf16* __restrict__ sl)
{
    __shared__ float red[8];
    const int tid  = threadIdx.x;
    const int lane = tid & 31, wid = tid >> 5;
    const size_t base = (size_t)blockIdx.x * NKK;

    float sv[16], wv[16];
    unsigned mbits = 0u;
    float mx = -INFINITY;
    #pragma unroll
    for (int i = 0; i < 16; i++) {
        const int idx = tid + i * 256;
        float v = sraw[base + idx];
        const int mm = mask[base + idx];
        wv[i] = wei[base + idx];
        if (mm) mbits |= (1u << i); else v = -INFINITY;
        sv[i] = v;
        mx = fmaxf(mx, v);
    }
    #pragma unroll
    for (int o = 16; o; o >>= 1) mx = fmaxf(mx, __shfl_xor_sync(0xffffffffu, mx, o));
    if (lane == 0) red[wid] = mx;
    __syncthreads();
    mx = red[0];
    #pragma unroll
    for (int w = 1; w < 8; w++) mx = fmaxf(mx, red[w]);

    float sum = 0.f;
    #pragma unroll
    for (int i = 0; i < 16; i++) { float p = expf(sv[i] - mx); sv[i] = p; sum += p; }
    #pragma unroll
    for (int o = 16; o; o >>= 1) sum += __shfl_xor_sync(0xffffffffu, sum, o);
    __syncthreads();
    if (lane == 0) red[wid] = sum;
    __syncthreads();
    sum = 0.f;
    #pragma unroll
    for (int w = 0; w < 8; w++) sum += red[w];
    const float inv = 1.0f / sum;

    float mx2 = -INFINITY;
    #pragma unroll
    for (int i = 0; i < 16; i++) {
        const float t = ((mbits >> i) & 1u) ? sv[i] * inv * wv[i] : -INFINITY;
        sv[i] = t;
        mx2 = fmaxf(mx2, t);
    }
    #pragma unroll
    for (int o = 16; o; o >>= 1) mx2 = fmaxf(mx2, __shfl_xor_sync(0xffffffffu, mx2, o));
    __syncthreads();
    if (lane == 0) red[wid] = mx2;
    __syncthreads();
    mx2 = red[0];
    #pragma unroll
    for (int w = 1; w < 8; w++) mx2 = fmaxf(mx2, red[w]);

    float sum2 = 0.f;
    #pragma unroll
    for (int i = 0; i < 16; i++) { float p = expf(sv[i] - mx2); sv[i] = p; sum2 += p; }
    #pragma unroll
    for (int o = 16; o; o >>= 1) sum2 += __shfl_xor_sync(0xffffffffu, sum2, o);
    __syncthreads();
    if (lane == 0) red[wid] = sum2;
    __syncthreads();
    sum2 = 0.f;
    #pragma unroll
    for (int w = 0; w < 8; w++) sum2 += red[w];
    const float inv2 = 1.0f / sum2;

    #pragma unroll
    for (int i = 0; i < 16; i++) {
        const float p = sv[i] * inv2;
        const int idx = tid + i * 256;
        sout[base + idx] = p;
        bf16 h, l;
        split_bf16(p, h, l);
        sh[base + idx] = h;
        sl[base + idx] = l;
    }
}

// ---------------------------------------------------------------------------
extern "C" void kernel_launch(void* const* d_in, const int* in_sizes, int n_in,
                              void* d_out, int out_size)
{
    const float* q    = (const float*)d_in[0];
    const float* k    = (const float*)d_in[1];
    const int*   mask = (const int*)  d_in[2];
    const float* wei  = (const float*)d_in[3];
    const float* Wq   = (const float*)d_in[4];
    const float* bq   = (const float*)d_in[5];
    const float* Wk   = (const float*)d_in[6];
    const float* bk   = (const float*)d_in[7];
    const float* Wp   = (const float*)d_in[8];
    const float* bp   = (const float*)d_in[9];

    float* out_ptr   = (float*)d_out;                 // [NQ, DIM]
    float* score_out = out_ptr + (size_t)NQ * DIM;    // [NQ, NKK]

    bf16 *qh, *ql, *kh, *kl, *Wqh, *Wql, *Wkh, *Wkl, *Wph, *Wpl;
    bf16 *qxh, *qxl, *kxh, *kxl, *kxTh, *kxTl, *sh, *sl, *avh, *avl;
    float* sraw;
    cudaGetSymbolAddress((void**)&qh, g_qh);   cudaGetSymbolAddress((void**)&ql, g_ql);
    cudaGetSymbolAddress((void**)&kh, g_kh);   cudaGetSymbolAddress((void**)&kl, g_kl);
    cudaGetSymbolAddress((void**)&Wqh, g_Wqh); cudaGetSymbolAddress((void**)&Wql, g_Wql);
    cudaGetSymbolAddress((void**)&Wkh, g_Wkh); cudaGetSymbolAddress((void**)&Wkl, g_Wkl);
    cudaGetSymbolAddress((void**)&Wph, g_Wph); cudaGetSymbolAddress((void**)&Wpl, g_Wpl);
    cudaGetSymbolAddress((void**)&qxh, g_qxh); cudaGetSymbolAddress((void**)&qxl, g_qxl);
    cudaGetSymbolAddress((void**)&kxh, g_kxh); cudaGetSymbolAddress((void**)&kxl, g_kxl);
    cudaGetSymbolAddress((void**)&kxTh, g_kxTh); cudaGetSymbolAddress((void**)&kxTl, g_kxTl);
    cudaGetSymbolAddress((void**)&sh, g_sh);   cudaGetSymbolAddress((void**)&sl, g_sl);
    cudaGetSymbolAddress((void**)&avh, g_avh); cudaGetSymbolAddress((void**)&avl, g_avl);
    cudaGetSymbolAddress((void**)&sraw, g_sraw);

    static bool attr_done = false;
    if (!attr_done) {
        cudaFuncSetAttribute(gemm_mma, cudaFuncAttributeMaxDynamicSharedMemorySize, SMEM_DYN);
        cudaFuncSetAttribute(gemm_proj, cudaFuncAttributeMaxDynamicSharedMemorySize, SMEM_DYN);
        attr_done = true;
    }

    const dim3 blk(256);
    // #0: all fp32 -> bf16 pair conversions
    conv_all<<<11264, 256>>>(q, k, Wq, Wk, Wp, qh, ql, kh, kl,
                             Wqh, Wql, Wkh, Wkl, Wph, Wpl);
    // #1: kx & qx projections, one launch
    gemm_proj<<<dim3(DIM / BN, NQ / BM, 2), blk, SMEM_DYN>>>(
        kh, kl, Wkh, Wkl, bk, kxh, kxl,
        qh, ql, Wqh, Wql, bq, qxh, qxl);
    // #2: kxT pair (for AV GEMM B-side)
    transpose2_bf16<<<dim3(DIM / 32, NKK / 32, 2), dim3(32, 8)>>>(
        kxh, kxTh, kxl, kxTl, NKK, DIM);
    // #3: sraw = qx @ kx^T
    gemm_mma<<<dim3(NKK / BN, NQ / BM), blk, SMEM_DYN>>>(
        qxh, qxl, kxh, kxl, nullptr, sraw, nullptr, nullptr, NKK, DIM);
    // #4: double masked softmax -> fp32 (d_out) + bf16 pair
    softmax2_kernel<<<NQ, 256>>>(sraw, mask, wei, score_out, sh, sl);
    // #5: av = score @ kxT^T
    gemm_mma<<<dim3(DIM / BN, NQ / BM), blk, SMEM_DYN>>>(
        sh, sl, kxTh, kxTl, nullptr, nullptr, avh, avl, DIM, NKK);
    // #6: out = av @ Wp^T + bp
    gemm_mma<<<dim3(DIM / BN, NQ / BM), blk, SMEM_DYN>>>(
        avh, avl, Wph, Wpl, bp, out_ptr, nullptr, nullptr, DIM, DIM);
}